// round 5
// baseline (speedup 1.0000x reference)
#include <cuda_runtime.h>
#include <math.h>

#define Bsz 4096
#define Tsz 64
#define Fsz 37
#define TB 4          // batch elements per CTA
#define NP 12         // TB * 3 timesteps
#define NT 128        // threads per CTA (one per hidden unit)
#define FDIM 150      // lin width
#define GATES 512
#define H 128

typedef unsigned long long ull;

// ---- global scratch: duplicated-pair packed LSTM weights ----
// layout: [f][j][c] of (w,w) f32x2 pairs, c = gate 0..3
__device__ ull g_wk[FDIM * GATES];   // 150*512*8B = 614KB
__device__ ull g_wr[H * GATES];      // 128*512*8B = 524KB

// shared memory layout (floats)
#define OFF_FEAT 0        // 12*37 = 444 (aliased by head buffers later)
#define OFF_T1M1 448      // 12*16 = 192
#define OFF_S1   640      // 12*32 = 384
#define OFF_LIN  1024     // 3*150*4 = 1800 (byte 4096, 16B aligned)
#define OFF_H    2824     // 128*4 = 512    (byte 11296, 16B aligned)
#define SMEM_FLOATS 3336  // 13344 bytes

struct Params {
    const float *feature;
    const float *w_m1, *b_m1, *w_m2, *b_m2;
    const float *w_t1, *b_t1, *w_t2, *b_t2;
    const float *w_s1, *b_s1, *w_s2, *b_s2;
    const float *w_lk, *w_lr, *b_l;
    const float *w_p1, *b_p1, *w_p2, *b_p2, *w_p3, *b_p3, *w_p4, *b_p4, *w_p5, *b_p5;
    float *out;
};

__device__ __forceinline__ float lrelu(float x) { return x >= 0.f ? x : 0.2f * x; }
__device__ __forceinline__ float sigm(float x) { return 1.f / (1.f + __expf(-x)); }

__device__ __forceinline__ ull pack2(float lo, float hi) {
    ull v;
    asm("mov.b64 %0, {%1, %2};" : "=l"(v) : "f"(lo), "f"(hi));
    return v;
}
__device__ __forceinline__ void unpack2(float &lo, float &hi, ull v) {
    asm("mov.b64 {%0, %1}, %2;" : "=f"(lo), "=f"(hi) : "l"(v));
}
__device__ __forceinline__ void ffma2(ull &acc, ull a, ull b) {
    asm("fma.rn.f32x2 %0, %1, %2, %0;" : "+l"(acc) : "l"(a), "l"(b));
}

// ---- pre-kernel: repack w_lk/w_lr as duplicated f32x2 pairs ----
__global__ void repack_kernel(const float *__restrict__ wlk,
                              const float *__restrict__ wlr) {
    int i = blockIdx.x * 256 + threadIdx.x;
    if (i < FDIM * GATES) {
        int f = i >> 9, cj = i & 511;
        int c = cj >> 7, j = cj & 127;
        float w = wlk[f * GATES + c * H + j];
        g_wk[(f * H + j) * 4 + c] = pack2(w, w);
    }
    if (i < H * GATES) {
        int f = i >> 9, cj = i & 511;
        int c = cj >> 7, j = cj & 127;
        float w = wlr[f * GATES + c * H + j];
        g_wr[(f * H + j) * 4 + c] = pack2(w, w);
    }
}

// lin transposed: [t][f][b], b contiguous (4 floats = 16B per row)
#define LIDX(t, f, b) (((t) * FDIM + (f)) * TB + (b))

__global__ void __launch_bounds__(NT) lstm_fused_kernel(Params P) {
    __shared__ __align__(16) float sm[SMEM_FLOATS];
    const int tid = threadIdx.x;
    const int bg0 = blockIdx.x * TB;

    float *feat = sm + OFF_FEAT;
    float *t1m1 = sm + OFF_T1M1;
    float *S1   = sm + OFF_S1;
    float *linT = sm + OFF_LIN;
    float *hT   = sm + OFF_H;

    // ---- load feature rows t=0..2 for 4 batch elems ----
    for (int i = tid; i < NP * Fsz; i += NT) {
        int p = i / Fsz, f = i % Fsz;
        int b = p / 3, t = p % 3;
        feat[p * Fsz + f] =
            P.feature[(size_t)(bg0 + b) * Tsz * Fsz + (size_t)t * Fsz + f];
    }
    __syncthreads();

    // ---- pass1: M1 (q<8) and T1 (q>=8), per (b,t) pair p ----
    for (int i = tid; i < NP * 16; i += NT) {
        int p = i >> 4, q = i & 15;
        const float *fr = feat + p * Fsz;
        float acc;
        if (q < 8) {
            acc = P.b_m1[q];
            #pragma unroll
            for (int f = 0; f < 3; ++f) acc += fr[33 + f] * P.w_m1[f * 8 + q];
            acc = lrelu(acc);
        } else {
            int j = q - 8;
            acc = P.b_t1[j];
            #pragma unroll
            for (int f = 0; f < Fsz; ++f) acc += fr[f] * P.w_t1[f * 8 + j];
            acc = lrelu(acc);
            acc = fabsf(acc);
        }
        t1m1[i] = acc;
    }
    __syncthreads();

    // ---- pass2: M -> lin[0:16], Tsk -> lin[16:32], Psk -> lin[32:48] ----
    for (int i = tid; i < NP * 32; i += NT) {
        int p = i >> 5, q = i & 31;
        int b = p / 3, t = p % 3;
        if (q < 16) {
            float acc = P.b_m2[q];
            #pragma unroll
            for (int k = 0; k < 8; ++k) acc += t1m1[p * 16 + k] * P.w_m2[k * 16 + q];
            linT[LIDX(t, q, b)] = lrelu(acc);
        } else {
            int j = q - 16;
            float acc = P.b_t2[j];
            #pragma unroll
            for (int k = 0; k < 8; ++k) acc += t1m1[p * 16 + 8 + k] * P.w_t2[k * 16 + j];
            float v = (acc >= 0.f) ? acc : -0.2f * acc;  // abs(lrelu)
            linT[LIDX(t, 16 + j, b)] = v;
            linT[LIDX(t, 32 + j, b)] = log1pf(v);
        }
    }
    // Pa -> lin[48], feature copy -> lin[113:150]
    for (int i = tid; i < NP * 38; i += NT) {
        int p = i / 38, q = i % 38;
        int b = p / 3, t = p % 3;
        if (q == 0) linT[LIDX(t, 48, b)] = log1pf(feat[p * Fsz + 31]);
        else        linT[LIDX(t, 113 + (q - 1), b)] = feat[p * Fsz + (q - 1)];
    }
    __syncthreads();

    // ---- pass3: S1 = lrelu(s_in @ w_s1 + b_s1) ----
    for (int i = tid; i < NP * 32; i += NT) {
        int p = i >> 5, j = i & 31;
        int b = p / 3, t = p % 3;
        float acc = P.b_s1[j];
        for (int f = 0; f < 49; ++f) acc += linT[LIDX(t, f, b)] * P.w_s1[f * 32 + j];
        const float *fr = feat + p * Fsz;
        #pragma unroll
        for (int e = 0; e < 6; ++e) acc += fr[27 + e] * P.w_s1[(49 + e) * 32 + j];
        #pragma unroll
        for (int e = 0; e < 3; ++e) acc += fr[33 + e] * P.w_s1[(55 + e) * 32 + j];
        S1[p * 32 + j] = lrelu(acc);
    }
    __syncthreads();

    // ---- pass4: S -> lin[49:113] ----
    for (int i = tid; i < NP * 64; i += NT) {
        int p = i >> 6, j = i & 63;
        int b = p / 3, t = p % 3;
        float acc = P.b_s2[j];
        #pragma unroll
        for (int k = 0; k < 32; ++k) acc += S1[p * 32 + k] * P.w_s2[k * 64 + j];
        linT[LIDX(t, 49 + j, b)] = lrelu(acc);
    }
    __syncthreads();

    // ---- LSTM: 3 timesteps. Thread tid owns hidden unit j=tid (gate
    // columns j, j+128, j+256, j+384 = i,f,g,o). Batch packed in f32x2
    // pairs; weights pre-duplicated in g_wk/g_wr; c-state in registers.
    {
        const int j = tid;
        ull bia[4];
        #pragma unroll
        for (int c = 0; c < 4; ++c) {
            float bv = P.b_l[j + c * H];
            bia[c] = pack2(bv, bv);
        }
        float cres[TB];
        #pragma unroll
        for (int b = 0; b < TB; ++b) cres[b] = 0.f;

        for (int t = 0; t < 3; ++t) {
            ull acc[4][2];
            #pragma unroll
            for (int c = 0; c < 4; ++c) {
                acc[c][0] = bia[c];
                acc[c][1] = bia[c];
            }

            // input GEMM: z += lin_t @ w_lk
            const ulonglong2 *wkp = (const ulonglong2 *)(g_wk) + j * 2;
            #pragma unroll 4
            for (int f = 0; f < FDIM; ++f) {
                ulonglong2 lv = *(const ulonglong2 *)(linT + (t * FDIM + f) * TB);
                ulonglong2 w01 = wkp[f * H * 2 + 0];
                ulonglong2 w23 = wkp[f * H * 2 + 1];
                ffma2(acc[0][0], lv.x, w01.x);
                ffma2(acc[0][1], lv.y, w01.x);
                ffma2(acc[1][0], lv.x, w01.y);
                ffma2(acc[1][1], lv.y, w01.y);
                ffma2(acc[2][0], lv.x, w23.x);
                ffma2(acc[2][1], lv.y, w23.x);
                ffma2(acc[3][0], lv.x, w23.y);
                ffma2(acc[3][1], lv.y, w23.y);
            }
            // recurrent GEMM: z += h @ w_lr  (h == 0 at t=0)
            if (t > 0) {
                const ulonglong2 *wrp = (const ulonglong2 *)(g_wr) + j * 2;
                #pragma unroll 4
                for (int f = 0; f < H; ++f) {
                    ulonglong2 lv = *(const ulonglong2 *)(hT + f * TB);
                    ulonglong2 w01 = wrp[f * H * 2 + 0];
                    ulonglong2 w23 = wrp[f * H * 2 + 1];
                    ffma2(acc[0][0], lv.x, w01.x);
                    ffma2(acc[0][1], lv.y, w01.x);
                    ffma2(acc[1][0], lv.x, w01.y);
                    ffma2(acc[1][1], lv.y, w01.y);
                    ffma2(acc[2][0], lv.x, w23.x);
                    ffma2(acc[2][1], lv.y, w23.x);
                    ffma2(acc[3][0], lv.x, w23.y);
                    ffma2(acc[3][1], lv.y, w23.y);
                }
            }

            // all reads of hT (this t) must finish before overwrite
            __syncthreads();

            // gates + state update, fully in registers
            float zi[TB], zf[TB], zg[TB], zo[TB], hv[TB];
            unpack2(zi[0], zi[1], acc[0][0]);
            unpack2(zi[2], zi[3], acc[0][1]);
            unpack2(zf[0], zf[1], acc[1][0]);
            unpack2(zf[2], zf[3], acc[1][1]);
            unpack2(zg[0], zg[1], acc[2][0]);
            unpack2(zg[2], zg[3], acc[2][1]);
            unpack2(zo[0], zo[1], acc[3][0]);
            unpack2(zo[2], zo[3], acc[3][1]);
            #pragma unroll
            for (int b = 0; b < TB; ++b) {
                float cv = sigm(zf[b]) * cres[b] + sigm(zi[b]) * lrelu(zg[b]);
                cres[b] = cv;
                hv[b] = sigm(zo[b]) * lrelu(cv);
            }
            *(float4 *)(hT + j * TB) = make_float4(hv[0], hv[1], hv[2], hv[3]);
            __syncthreads();
        }
    }

    // ---- head at t=2 (buffers alias dead front-end smem) ----
    float *d1 = sm;        // 4*64 = 256
    float *d2 = sm + 256;  // 4*32 = 128
    float *d3 = sm + 384;  // 4*16 = 64
    float *d4 = sm + 448;  // 4*8  = 32
    float *d5 = sm + 480;  // 4*3  = 12

    for (int i = tid; i < TB * 64; i += NT) {
        int b = i >> 6, j = i & 63;
        float acc = P.b_p1[j];
        for (int k = 0; k < H; ++k) acc += hT[k * TB + b] * P.w_p1[k * 64 + j];
        d1[i] = lrelu(acc);
    }
    __syncthreads();
    for (int i = tid; i < TB * 32; i += NT) {
        int b = i >> 5, j = i & 31;
        float acc = P.b_p2[j];
        #pragma unroll
        for (int k = 0; k < 64; ++k) acc += d1[b * 64 + k] * P.w_p2[k * 32 + j];
        d2[i] = lrelu(acc);
    }
    __syncthreads();
    for (int i = tid; i < TB * 16; i += NT) {
        int b = i >> 4, j = i & 15;
        float acc = P.b_p3[j];
        #pragma unroll
        for (int k = 0; k < 32; ++k) acc += d2[b * 32 + k] * P.w_p3[k * 16 + j];
        d3[i] = lrelu(acc);
    }
    __syncthreads();
    for (int i = tid; i < TB * 8; i += NT) {
        int b = i >> 3, j = i & 7;
        float acc = P.b_p4[j];
        #pragma unroll
        for (int k = 0; k < 16; ++k) acc += d3[b * 16 + k] * P.w_p4[k * 8 + j];
        d4[i] = lrelu(acc);
    }
    __syncthreads();
    for (int i = tid; i < TB * 3; i += NT) {
        int b = i / 3, j = i % 3;
        float acc = P.b_p5[j];
        #pragma unroll
        for (int k = 0; k < 8; ++k) acc += d4[b * 8 + k] * P.w_p5[k * 3 + j];
        d5[i] = lrelu(acc);
    }
    __syncthreads();

    // ---- softmax + write both outputs ----
    if (tid < TB) {
        int b = tid;
        float l0 = d5[b * 3 + 0], l1 = d5[b * 3 + 1], l2 = d5[b * 3 + 2];
        float m = fmaxf(l0, fmaxf(l1, l2));
        float e0 = __expf(l0 - m), e1 = __expf(l1 - m), e2 = __expf(l2 - m);
        float inv = 1.f / (e0 + e1 + e2);
        float o0 = e0 * inv, o1 = e1 * inv, o2 = e2 * inv;
        size_t gb = (size_t)(bg0 + b);
        float *outp = P.out + gb * 3;
        outp[0] = o0; outp[1] = o1; outp[2] = o2;
        float *xp = P.out + (size_t)Bsz * 3 + gb * 13;
        const float *fsrc = P.feature + gb * Tsz * Fsz + 2 * Fsz + 27;
        #pragma unroll
        for (int q = 0; q < 10; ++q) xp[q] = fsrc[q];
        xp[10] = o0; xp[11] = o1; xp[12] = o2;
    }
}

extern "C" void kernel_launch(void *const *d_in, const int *in_sizes, int n_in,
                              void *d_out, int out_size) {
    Params P;
    P.feature = (const float *)d_in[0];
    P.w_m1 = (const float *)d_in[1];  P.b_m1 = (const float *)d_in[2];
    P.w_m2 = (const float *)d_in[3];  P.b_m2 = (const float *)d_in[4];
    P.w_t1 = (const float *)d_in[5];  P.b_t1 = (const float *)d_in[6];
    P.w_t2 = (const float *)d_in[7];  P.b_t2 = (const float *)d_in[8];
    P.w_s1 = (const float *)d_in[9];  P.b_s1 = (const float *)d_in[10];
    P.w_s2 = (const float *)d_in[11]; P.b_s2 = (const float *)d_in[12];
    P.w_lk = (const float *)d_in[13];
    P.w_lr = (const float *)d_in[14];
    P.b_l  = (const float *)d_in[15];
    P.w_p1 = (const float *)d_in[16]; P.b_p1 = (const float *)d_in[17];
    P.w_p2 = (const float *)d_in[18]; P.b_p2 = (const float *)d_in[19];
    P.w_p3 = (const float *)d_in[20]; P.b_p3 = (const float *)d_in[21];
    P.w_p4 = (const float *)d_in[22]; P.b_p4 = (const float *)d_in[23];
    P.w_p5 = (const float *)d_in[24]; P.b_p5 = (const float *)d_in[25];
    P.out = (float *)d_out;

    repack_kernel<<<(FDIM * GATES + 255) / 256, 256>>>(P.w_lk, P.w_lr);
    lstm_fused_kernel<<<Bsz / TB, NT>>>(P);
}

// round 6
// speedup vs baseline: 1.5877x; 1.5877x over previous
#include <cuda_runtime.h>
#include <math.h>

#define Bsz 4096
#define Tsz 64
#define Fsz 37
#define TB 8          // batch elements per CTA
#define NP 24         // TB * 3 timesteps
#define NT 256        // 2 f-split halves x 128 hidden units
#define FDIM 150      // lin width
#define GATES 512
#define H 128

typedef unsigned long long ull;

// shared memory layout (floats)
#define OFF_FEAT 0        // 24*37 = 888  (aliased by head buffers later)
#define OFF_T1M1 888      // 24*16 = 384
#define OFF_S1   1272     // 24*32 = 768
#define OFF_LIN  2040     // 3*150*8 = 3600 (byte 8160, 16B aligned)
#define OFF_H    5640     // 128*8 = 1024   (byte 22560, 32B aligned)
#define OFF_Z    6664     // 4*128*8 = 4096 (byte 26656, 16B aligned)
#define SMEM_FLOATS 10760 // 43040 bytes < 48KB static limit

struct Params {
    const float *feature;
    const float *w_m1, *b_m1, *w_m2, *b_m2;
    const float *w_t1, *b_t1, *w_t2, *b_t2;
    const float *w_s1, *b_s1, *w_s2, *b_s2;
    const float *w_lk, *w_lr, *b_l;
    const float *w_p1, *b_p1, *w_p2, *b_p2, *w_p3, *b_p3, *w_p4, *b_p4, *w_p5, *b_p5;
    float *out;
};

__device__ __forceinline__ float lrelu(float x) { return x >= 0.f ? x : 0.2f * x; }
__device__ __forceinline__ float sigm(float x) { return 1.f / (1.f + __expf(-x)); }

__device__ __forceinline__ ull pack2(float lo, float hi) {
    ull v;
    asm("mov.b64 %0, {%1, %2};" : "=l"(v) : "f"(lo), "f"(hi));
    return v;
}
__device__ __forceinline__ void unpack2(float &lo, float &hi, ull v) {
    asm("mov.b64 {%0, %1}, %2;" : "=f"(lo), "=f"(hi) : "l"(v));
}
__device__ __forceinline__ void ffma2(ull &acc, ull a, ull b) {
    asm("fma.rn.f32x2 %0, %1, %2, %0;" : "+l"(acc) : "l"(a), "l"(b));
}
__device__ __forceinline__ void add2(ull &acc, ull a) {
    asm("add.rn.f32x2 %0, %0, %1;" : "+l"(acc) : "l"(a));
}

// lin transposed: [t][f][b], b contiguous (8 floats = 32B per row)
#define LIDX(t, f, b) (((t) * FDIM + (f)) * TB + (b))

__global__ void __launch_bounds__(NT) lstm_fused_kernel(Params P) {
    __shared__ __align__(32) float sm[SMEM_FLOATS];
    const int tid = threadIdx.x;
    const int bg0 = blockIdx.x * TB;

    float *feat = sm + OFF_FEAT;
    float *t1m1 = sm + OFF_T1M1;
    float *S1   = sm + OFF_S1;
    float *linT = sm + OFF_LIN;
    float *hT   = sm + OFF_H;
    ull   *zpart = (ull *)(sm + OFF_Z);   // [4 gates][128 j][4 pairs] of f32x2

    // ---- load feature rows t=0..2 for 8 batch elems ----
    for (int i = tid; i < NP * Fsz; i += NT) {
        int p = i / Fsz, f = i % Fsz;
        int b = p / 3, t = p % 3;
        feat[p * Fsz + f] =
            P.feature[(size_t)(bg0 + b) * Tsz * Fsz + (size_t)t * Fsz + f];
    }
    __syncthreads();

    // ---- pass1: M1 (q<8) and T1 (q>=8), per (b,t) pair p ----
    for (int i = tid; i < NP * 16; i += NT) {
        int p = i >> 4, q = i & 15;
        const float *fr = feat + p * Fsz;
        float acc;
        if (q < 8) {
            acc = P.b_m1[q];
            #pragma unroll
            for (int f = 0; f < 3; ++f) acc += fr[33 + f] * P.w_m1[f * 8 + q];
            acc = lrelu(acc);
        } else {
            int j = q - 8;
            acc = P.b_t1[j];
            #pragma unroll
            for (int f = 0; f < Fsz; ++f) acc += fr[f] * P.w_t1[f * 8 + j];
            acc = lrelu(acc);
            acc = fabsf(acc);
        }
        t1m1[i] = acc;
    }
    __syncthreads();

    // ---- pass2: M -> lin[0:16], Tsk -> lin[16:32], Psk -> lin[32:48] ----
    for (int i = tid; i < NP * 32; i += NT) {
        int p = i >> 5, q = i & 31;
        int b = p / 3, t = p % 3;
        if (q < 16) {
            float acc = P.b_m2[q];
            #pragma unroll
            for (int k = 0; k < 8; ++k) acc += t1m1[p * 16 + k] * P.w_m2[k * 16 + q];
            linT[LIDX(t, q, b)] = lrelu(acc);
        } else {
            int j = q - 16;
            float acc = P.b_t2[j];
            #pragma unroll
            for (int k = 0; k < 8; ++k) acc += t1m1[p * 16 + 8 + k] * P.w_t2[k * 16 + j];
            float v = (acc >= 0.f) ? acc : -0.2f * acc;  // abs(lrelu)
            linT[LIDX(t, 16 + j, b)] = v;
            linT[LIDX(t, 32 + j, b)] = log1pf(v);
        }
    }
    // Pa -> lin[48], feature copy -> lin[113:150]
    for (int i = tid; i < NP * 38; i += NT) {
        int p = i / 38, q = i % 38;
        int b = p / 3, t = p % 3;
        if (q == 0) linT[LIDX(t, 48, b)] = log1pf(feat[p * Fsz + 31]);
        else        linT[LIDX(t, 113 + (q - 1), b)] = feat[p * Fsz + (q - 1)];
    }
    __syncthreads();

    // ---- pass3: S1 = lrelu(s_in @ w_s1 + b_s1) ----
    for (int i = tid; i < NP * 32; i += NT) {
        int p = i >> 5, j = i & 31;
        int b = p / 3, t = p % 3;
        float acc = P.b_s1[j];
        for (int f = 0; f < 49; ++f) acc += linT[LIDX(t, f, b)] * P.w_s1[f * 32 + j];
        const float *fr = feat + p * Fsz;
        #pragma unroll
        for (int e = 0; e < 6; ++e) acc += fr[27 + e] * P.w_s1[(49 + e) * 32 + j];
        #pragma unroll
        for (int e = 0; e < 3; ++e) acc += fr[33 + e] * P.w_s1[(55 + e) * 32 + j];
        S1[p * 32 + j] = lrelu(acc);
    }
    __syncthreads();

    // ---- pass4: S -> lin[49:113] ----
    for (int i = tid; i < NP * 64; i += NT) {
        int p = i >> 6, j = i & 63;
        int b = p / 3, t = p % 3;
        float acc = P.b_s2[j];
        #pragma unroll
        for (int k = 0; k < 32; ++k) acc += S1[p * 32 + k] * P.w_s2[k * 64 + j];
        linT[LIDX(t, 49 + j, b)] = lrelu(acc);
    }
    __syncthreads();

    // ---- LSTM: 3 timesteps. Thread (s, j): j = tid&127 owns hidden unit j
    // (gate columns j, j+128, j+256, j+384 = i,f,g,o); s = tid>>7 selects the
    // f-split half. s=0: f in [0,75) + k in [0,64); s=1: f in [75,150) +
    // k in [64,128). s=1 publishes partial z via zpart, s=0 reduces, applies
    // gates, keeps c in registers and writes h.
    {
        const int j = tid & (H - 1);
        const int s = tid >> 7;
        const float *wk = P.w_lk + j;
        const float *wr = P.w_lr + j;
        ull bia[4];
        #pragma unroll
        for (int c = 0; c < 4; ++c) {
            float bv = (s == 0) ? P.b_l[j + c * H] : 0.f;
            bia[c] = pack2(bv, bv);
        }
        float cres[TB];
        #pragma unroll
        for (int b = 0; b < TB; ++b) cres[b] = 0.f;

        const int f0 = s * 75, f1 = f0 + 75;
        const int k0 = s * 64, k1 = k0 + 64;

        for (int t = 0; t < 3; ++t) {
            ull acc[4][4];
            #pragma unroll
            for (int c = 0; c < 4; ++c)
                #pragma unroll
                for (int p = 0; p < 4; ++p) acc[c][p] = bia[c];

            // input GEMM half: z += lin_t[f0:f1] @ w_lk[f0:f1]
            #pragma unroll 5
            for (int f = f0; f < f1; ++f) {
                const ulonglong2 *lp =
                    (const ulonglong2 *)(linT + (t * FDIM + f) * TB);
                ulonglong2 u0 = lp[0];
                ulonglong2 u1 = lp[1];
                #pragma unroll
                for (int c = 0; c < 4; ++c) {
                    float w = __ldg(wk + f * GATES + c * H);
                    ull wd = pack2(w, w);
                    ffma2(acc[c][0], u0.x, wd);
                    ffma2(acc[c][1], u0.y, wd);
                    ffma2(acc[c][2], u1.x, wd);
                    ffma2(acc[c][3], u1.y, wd);
                }
            }
            // recurrent GEMM half: z += h[k0:k1] @ w_lr[k0:k1]  (h==0 at t=0)
            if (t > 0) {
                #pragma unroll 4
                for (int f = k0; f < k1; ++f) {
                    const ulonglong2 *hp = (const ulonglong2 *)(hT + f * TB);
                    ulonglong2 u0 = hp[0];
                    ulonglong2 u1 = hp[1];
                    #pragma unroll
                    for (int c = 0; c < 4; ++c) {
                        float w = __ldg(wr + f * GATES + c * H);
                        ull wd = pack2(w, w);
                        ffma2(acc[c][0], u0.x, wd);
                        ffma2(acc[c][1], u0.y, wd);
                        ffma2(acc[c][2], u1.x, wd);
                        ffma2(acc[c][3], u1.y, wd);
                    }
                }
            }

            // s=1 publishes its partial z (also ends hT reads for this t)
            __syncthreads();
            if (s == 1) {
                ulonglong2 *zr = (ulonglong2 *)(zpart);
                #pragma unroll
                for (int c = 0; c < 4; ++c) {
                    zr[(c * H + j) * 2 + 0] = make_ulonglong2(acc[c][0], acc[c][1]);
                    zr[(c * H + j) * 2 + 1] = make_ulonglong2(acc[c][2], acc[c][3]);
                }
            }
            __syncthreads();

            // s=0 reduces + gates + state update, fully in registers
            if (s == 0) {
                const ulonglong2 *zr = (const ulonglong2 *)(zpart);
                #pragma unroll
                for (int c = 0; c < 4; ++c) {
                    ulonglong2 p0 = zr[(c * H + j) * 2 + 0];
                    ulonglong2 p1 = zr[(c * H + j) * 2 + 1];
                    add2(acc[c][0], p0.x);
                    add2(acc[c][1], p0.y);
                    add2(acc[c][2], p1.x);
                    add2(acc[c][3], p1.y);
                }
                float zi[TB], zf[TB], zg[TB], zo[TB], hv[TB];
                #pragma unroll
                for (int p = 0; p < 4; ++p) {
                    unpack2(zi[2 * p], zi[2 * p + 1], acc[0][p]);
                    unpack2(zf[2 * p], zf[2 * p + 1], acc[1][p]);
                    unpack2(zg[2 * p], zg[2 * p + 1], acc[2][p]);
                    unpack2(zo[2 * p], zo[2 * p + 1], acc[3][p]);
                }
                #pragma unroll
                for (int b = 0; b < TB; ++b) {
                    float cv = sigm(zf[b]) * cres[b] + sigm(zi[b]) * lrelu(zg[b]);
                    cres[b] = cv;
                    hv[b] = sigm(zo[b]) * lrelu(cv);
                }
                float4 *hrow = (float4 *)(hT + j * TB);
                hrow[0] = make_float4(hv[0], hv[1], hv[2], hv[3]);
                hrow[1] = make_float4(hv[4], hv[5], hv[6], hv[7]);
            }
            __syncthreads();
        }
    }

    // ---- head at t=2 (buffers alias dead front-end smem) ----
    float *d1 = sm;        // 8*64
    float *d2 = sm + 512;  // 8*32
    float *d3 = sm + 768;  // 8*16
    float *d4 = sm + 896;  // 8*8
    float *d5 = sm + 960;  // 8*3

    for (int i = tid; i < TB * 64; i += NT) {
        int b = i >> 6, j = i & 63;
        float acc = P.b_p1[j];
        for (int k = 0; k < H; ++k) acc += hT[k * TB + b] * P.w_p1[k * 64 + j];
        d1[i] = lrelu(acc);
    }
    __syncthreads();
    for (int i = tid; i < TB * 32; i += NT) {
        int b = i >> 5, j = i & 31;
        float acc = P.b_p2[j];
        #pragma unroll
        for (int k = 0; k < 64; ++k) acc += d1[b * 64 + k] * P.w_p2[k * 32 + j];
        d2[i] = lrelu(acc);
    }
    __syncthreads();
    for (int i = tid; i < TB * 16; i += NT) {
        int b = i >> 4, j = i & 15;
        float acc = P.b_p3[j];
        #pragma unroll
        for (int k = 0; k < 32; ++k) acc += d2[b * 32 + k] * P.w_p3[k * 16 + j];
        d3[i] = lrelu(acc);
    }
    __syncthreads();
    for (int i = tid; i < TB * 8; i += NT) {
        int b = i >> 3, j = i & 7;
        float acc = P.b_p4[j];
        #pragma unroll
        for (int k = 0; k < 16; ++k) acc += d3[b * 16 + k] * P.w_p4[k * 8 + j];
        d4[i] = lrelu(acc);
    }
    __syncthreads();
    for (int i = tid; i < TB * 3; i += NT) {
        int b = i / 3, j = i % 3;
        float acc = P.b_p5[j];
        #pragma unroll
        for (int k = 0; k < 8; ++k) acc += d4[b * 8 + k] * P.w_p5[k * 3 + j];
        d5[i] = lrelu(acc);
    }
    __syncthreads();

    // ---- softmax + write both outputs ----
    if (tid < TB) {
        int b = tid;
        float l0 = d5[b * 3 + 0], l1 = d5[b * 3 + 1], l2 = d5[b * 3 + 2];
        float m = fmaxf(l0, fmaxf(l1, l2));
        float e0 = __expf(l0 - m), e1 = __expf(l1 - m), e2 = __expf(l2 - m);
        float inv = 1.f / (e0 + e1 + e2);
        float o0 = e0 * inv, o1 = e1 * inv, o2 = e2 * inv;
        size_t gb = (size_t)(bg0 + b);
        float *outp = P.out + gb * 3;
        outp[0] = o0; outp[1] = o1; outp[2] = o2;
        float *xp = P.out + (size_t)Bsz * 3 + gb * 13;
        const float *fsrc = P.feature + gb * Tsz * Fsz + 2 * Fsz + 27;
        #pragma unroll
        for (int q = 0; q < 10; ++q) xp[q] = fsrc[q];
        xp[10] = o0; xp[11] = o1; xp[12] = o2;
    }
}

extern "C" void kernel_launch(void *const *d_in, const int *in_sizes, int n_in,
                              void *d_out, int out_size) {
    Params P;
    P.feature = (const float *)d_in[0];
    P.w_m1 = (const float *)d_in[1];  P.b_m1 = (const float *)d_in[2];
    P.w_m2 = (const float *)d_in[3];  P.b_m2 = (const float *)d_in[4];
    P.w_t1 = (const float *)d_in[5];  P.b_t1 = (const float *)d_in[6];
    P.w_t2 = (const float *)d_in[7];  P.b_t2 = (const float *)d_in[8];
    P.w_s1 = (const float *)d_in[9];  P.b_s1 = (const float *)d_in[10];
    P.w_s2 = (const float *)d_in[11]; P.b_s2 = (const float *)d_in[12];
    P.w_lk = (const float *)d_in[13];
    P.w_lr = (const float *)d_in[14];
    P.b_l  = (const float *)d_in[15];
    P.w_p1 = (const float *)d_in[16]; P.b_p1 = (const float *)d_in[17];
    P.w_p2 = (const float *)d_in[18]; P.b_p2 = (const float *)d_in[19];
    P.w_p3 = (const float *)d_in[20]; P.b_p3 = (const float *)d_in[21];
    P.w_p4 = (const float *)d_in[22]; P.b_p4 = (const float *)d_in[23];
    P.w_p5 = (const float *)d_in[24]; P.b_p5 = (const float *)d_in[25];
    P.out = (float *)d_out;

    lstm_fused_kernel<<<Bsz / TB, NT>>>(P);
}

// round 7
// speedup vs baseline: 1.8320x; 1.1539x over previous
#include <cuda_runtime.h>
#include <math.h>

#define Bsz 4096
#define Tsz 64
#define Fsz 37
#define TB 4          // batch elements per CTA
#define NP 12         // TB * 3 timesteps
#define NT 128        // threads per CTA (one per hidden unit)
#define FDIM 150      // lin width
#define FP2 75        // FDIM/2 f-pairs
#define KP2 64        // H/2 k-pairs
#define GATES 512
#define H 128

typedef unsigned long long ull;

// ---- global scratch: f-pair packed LSTM weights (same bytes as originals) ----
// g_wk2[(c*FP2 + fp)*H + j] = ( wlk[2fp][c*128+j] , wlk[2fp+1][c*128+j] )
// g_wr2[(c*KP2 + kp)*H + j] = ( wlr[2kp][c*128+j] , wlr[2kp+1][c*128+j] )
__device__ ull g_wk2[4 * FP2 * H];   // 307 KB
__device__ ull g_wr2[4 * KP2 * H];   // 262 KB

// shared memory layout (floats)
#define OFF_FEAT 0        // 12*37 = 444 (aliased by head buffers later)
#define OFF_T1M1 448      // 12*16 = 192
#define OFF_S1   640      // 12*32 = 384
#define OFF_LIN  1024     // 3*4*150 = 1800 (byte 4096; rows 600B -> 8B aligned)
#define OFF_H    2824     // 4*128 = 512    (byte 11296, 32B aligned)
#define SMEM_FLOATS 3336  // 13344 bytes

struct Params {
    const float *feature;
    const float *w_m1, *b_m1, *w_m2, *b_m2;
    const float *w_t1, *b_t1, *w_t2, *b_t2;
    const float *w_s1, *b_s1, *w_s2, *b_s2;
    const float *w_lk, *w_lr, *b_l;
    const float *w_p1, *b_p1, *w_p2, *b_p2, *w_p3, *b_p3, *w_p4, *b_p4, *w_p5, *b_p5;
    float *out;
};

__device__ __forceinline__ float lrelu(float x) { return x >= 0.f ? x : 0.2f * x; }
__device__ __forceinline__ float sigm(float x) { return 1.f / (1.f + __expf(-x)); }

__device__ __forceinline__ ull pack2(float lo, float hi) {
    ull v;
    asm("mov.b64 %0, {%1, %2};" : "=l"(v) : "f"(lo), "f"(hi));
    return v;
}
__device__ __forceinline__ void unpack2(float &lo, float &hi, ull v) {
    asm("mov.b64 {%0, %1}, %2;" : "=f"(lo), "=f"(hi) : "l"(v));
}
__device__ __forceinline__ void ffma2(ull &acc, ull a, ull b) {
    asm("fma.rn.f32x2 %0, %1, %2, %0;" : "+l"(acc) : "l"(a), "l"(b));
}

// ---- pre-kernel: repack w_lk/w_lr into f-pair float2 streams ----
__global__ void repack_kernel(const float *__restrict__ wlk,
                              const float *__restrict__ wlr) {
    int i = blockIdx.x * 256 + threadIdx.x;
    if (i < 4 * FP2 * H) {
        int c = i / (FP2 * H), r = i % (FP2 * H);
        int fp = r / H, j = r % H;
        g_wk2[i] = pack2(wlk[(2 * fp) * GATES + c * H + j],
                         wlk[(2 * fp + 1) * GATES + c * H + j]);
    }
    if (i < 4 * KP2 * H) {
        int c = i / (KP2 * H), r = i % (KP2 * H);
        int kp = r / H, j = r % H;
        g_wr2[i] = pack2(wlr[(2 * kp) * GATES + c * H + j],
                         wlr[(2 * kp + 1) * GATES + c * H + j]);
    }
}

// lin batch-major: [t][b][f], f contiguous (150 floats = 600B per row)
#define LIDX(t, f, b) (((t) * TB + (b)) * FDIM + (f))

__global__ void __launch_bounds__(NT) lstm_fused_kernel(Params P) {
    __shared__ __align__(32) float sm[SMEM_FLOATS];
    const int tid = threadIdx.x;
    const int bg0 = blockIdx.x * TB;

    float *feat = sm + OFF_FEAT;
    float *t1m1 = sm + OFF_T1M1;
    float *S1   = sm + OFF_S1;
    float *linB = sm + OFF_LIN;
    float *hB   = sm + OFF_H;     // [b][k]

    // ---- load feature rows t=0..2 for 4 batch elems ----
    for (int i = tid; i < NP * Fsz; i += NT) {
        int p = i / Fsz, f = i % Fsz;
        int b = p / 3, t = p % 3;
        feat[p * Fsz + f] =
            P.feature[(size_t)(bg0 + b) * Tsz * Fsz + (size_t)t * Fsz + f];
    }
    __syncthreads();

    // ---- pass1: M1 (q<8) and T1 (q>=8), per (b,t) pair p ----
    for (int i = tid; i < NP * 16; i += NT) {
        int p = i >> 4, q = i & 15;
        const float *fr = feat + p * Fsz;
        float acc;
        if (q < 8) {
            acc = P.b_m1[q];
            #pragma unroll
            for (int f = 0; f < 3; ++f) acc += fr[33 + f] * P.w_m1[f * 8 + q];
            acc = lrelu(acc);
        } else {
            int j = q - 8;
            acc = P.b_t1[j];
            #pragma unroll
            for (int f = 0; f < Fsz; ++f) acc += fr[f] * P.w_t1[f * 8 + j];
            acc = lrelu(acc);
            acc = fabsf(acc);
        }
        t1m1[i] = acc;
    }
    __syncthreads();

    // ---- pass2: M -> lin[0:16], Tsk -> lin[16:32], Psk -> lin[32:48] ----
    for (int i = tid; i < NP * 32; i += NT) {
        int p = i >> 5, q = i & 31;
        int b = p / 3, t = p % 3;
        if (q < 16) {
            float acc = P.b_m2[q];
            #pragma unroll
            for (int k = 0; k < 8; ++k) acc += t1m1[p * 16 + k] * P.w_m2[k * 16 + q];
            linB[LIDX(t, q, b)] = lrelu(acc);
        } else {
            int j = q - 16;
            float acc = P.b_t2[j];
            #pragma unroll
            for (int k = 0; k < 8; ++k) acc += t1m1[p * 16 + 8 + k] * P.w_t2[k * 16 + j];
            float v = (acc >= 0.f) ? acc : -0.2f * acc;  // abs(lrelu)
            linB[LIDX(t, 16 + j, b)] = v;
            linB[LIDX(t, 32 + j, b)] = log1pf(v);
        }
    }
    // Pa -> lin[48], feature copy -> lin[113:150]
    for (int i = tid; i < NP * 38; i += NT) {
        int p = i / 38, q = i % 38;
        int b = p / 3, t = p % 3;
        if (q == 0) linB[LIDX(t, 48, b)] = log1pf(feat[p * Fsz + 31]);
        else        linB[LIDX(t, 113 + (q - 1), b)] = feat[p * Fsz + (q - 1)];
    }
    __syncthreads();

    // ---- pass3: S1 = lrelu(s_in @ w_s1 + b_s1) ----
    for (int i = tid; i < NP * 32; i += NT) {
        int p = i >> 5, j = i & 31;
        int b = p / 3, t = p % 3;
        float acc = P.b_s1[j];
        for (int f = 0; f < 49; ++f) acc += linB[LIDX(t, f, b)] * P.w_s1[f * 32 + j];
        const float *fr = feat + p * Fsz;
        #pragma unroll
        for (int e = 0; e < 6; ++e) acc += fr[27 + e] * P.w_s1[(49 + e) * 32 + j];
        #pragma unroll
        for (int e = 0; e < 3; ++e) acc += fr[33 + e] * P.w_s1[(55 + e) * 32 + j];
        S1[p * 32 + j] = lrelu(acc);
    }
    __syncthreads();

    // ---- pass4: S -> lin[49:113] ----
    for (int i = tid; i < NP * 64; i += NT) {
        int p = i >> 6, j = i & 63;
        int b = p / 3, t = p % 3;
        float acc = P.b_s2[j];
        #pragma unroll
        for (int k = 0; k < 32; ++k) acc += S1[p * 32 + k] * P.w_s2[k * 64 + j];
        linB[LIDX(t, 49 + j, b)] = lrelu(acc);
    }
    __syncthreads();

    // ---- LSTM: 3 timesteps. Thread tid owns hidden unit j=tid (gate
    // columns j, j+128, j+256, j+384 = i,f,g,o). f32x2 lanes hold TWO
    // CONSECUTIVE f values (f-pair reduction); weights pre-paired in
    // g_wk2/g_wr2 (coalesced across j); activations broadcast from smem
    // batch-major rows. Horizontal lane-add once per timestep.
    {
        const int j = tid;
        const ull *wk0 = g_wk2 + 0 * FP2 * H + j;
        const ull *wk1 = g_wk2 + 1 * FP2 * H + j;
        const ull *wk2 = g_wk2 + 2 * FP2 * H + j;
        const ull *wk3 = g_wk2 + 3 * FP2 * H + j;
        const ull *wr0 = g_wr2 + 0 * KP2 * H + j;
        const ull *wr1 = g_wr2 + 1 * KP2 * H + j;
        const ull *wr2 = g_wr2 + 2 * KP2 * H + j;
        const ull *wr3 = g_wr2 + 3 * KP2 * H + j;
        float bi0 = P.b_l[j], bi1 = P.b_l[j + H];
        float bi2 = P.b_l[j + 2 * H], bi3 = P.b_l[j + 3 * H];
        float cres[TB];
        #pragma unroll
        for (int b = 0; b < TB; ++b) cres[b] = 0.f;

        for (int t = 0; t < 3; ++t) {
            ull acc[4][TB];   // [gate][batch], lanes = (even-f, odd-f) partials
            #pragma unroll
            for (int b = 0; b < TB; ++b) {
                acc[0][b] = pack2(bi0, 0.f);
                acc[1][b] = pack2(bi1, 0.f);
                acc[2][b] = pack2(bi2, 0.f);
                acc[3][b] = pack2(bi3, 0.f);
            }

            // input GEMM: z += lin_t @ w_lk   (75 f-pairs)
            {
                const ull *l0 = (const ull *)(linB + (t * TB + 0) * FDIM);
                const ull *l1 = (const ull *)(linB + (t * TB + 1) * FDIM);
                const ull *l2 = (const ull *)(linB + (t * TB + 2) * FDIM);
                const ull *l3 = (const ull *)(linB + (t * TB + 3) * FDIM);
                #pragma unroll 5
                for (int fp = 0; fp < FP2; ++fp) {
                    ull a0 = l0[fp], a1 = l1[fp], a2 = l2[fp], a3 = l3[fp];
                    ull w0 = wk0[fp * H];
                    ull w1 = wk1[fp * H];
                    ull w2 = wk2[fp * H];
                    ull w3 = wk3[fp * H];
                    ffma2(acc[0][0], a0, w0); ffma2(acc[0][1], a1, w0);
                    ffma2(acc[0][2], a2, w0); ffma2(acc[0][3], a3, w0);
                    ffma2(acc[1][0], a0, w1); ffma2(acc[1][1], a1, w1);
                    ffma2(acc[1][2], a2, w1); ffma2(acc[1][3], a3, w1);
                    ffma2(acc[2][0], a0, w2); ffma2(acc[2][1], a1, w2);
                    ffma2(acc[2][2], a2, w2); ffma2(acc[2][3], a3, w2);
                    ffma2(acc[3][0], a0, w3); ffma2(acc[3][1], a1, w3);
                    ffma2(acc[3][2], a2, w3); ffma2(acc[3][3], a3, w3);
                }
            }
            // recurrent GEMM: z += h @ w_lr   (64 k-pairs; h==0 at t=0)
            if (t > 0) {
                const ull *h0 = (const ull *)(hB + 0 * H);
                const ull *h1 = (const ull *)(hB + 1 * H);
                const ull *h2 = (const ull *)(hB + 2 * H);
                const ull *h3 = (const ull *)(hB + 3 * H);
                #pragma unroll 8
                for (int kp = 0; kp < KP2; ++kp) {
                    ull a0 = h0[kp], a1 = h1[kp], a2 = h2[kp], a3 = h3[kp];
                    ull w0 = wr0[kp * H];
                    ull w1 = wr1[kp * H];
                    ull w2 = wr2[kp * H];
                    ull w3 = wr3[kp * H];
                    ffma2(acc[0][0], a0, w0); ffma2(acc[0][1], a1, w0);
                    ffma2(acc[0][2], a2, w0); ffma2(acc[0][3], a3, w0);
                    ffma2(acc[1][0], a0, w1); ffma2(acc[1][1], a1, w1);
                    ffma2(acc[1][2], a2, w1); ffma2(acc[1][3], a3, w1);
                    ffma2(acc[2][0], a0, w2); ffma2(acc[2][1], a1, w2);
                    ffma2(acc[2][2], a2, w2); ffma2(acc[2][3], a3, w2);
                    ffma2(acc[3][0], a0, w3); ffma2(acc[3][1], a1, w3);
                    ffma2(acc[3][2], a2, w3); ffma2(acc[3][3], a3, w3);
                }
            }

            // all reads of hB (this t) must finish before overwrite
            __syncthreads();

            // horizontal lane-add + gates + state update, in registers
            #pragma unroll
            for (int b = 0; b < TB; ++b) {
                float zi_l, zi_h, zf_l, zf_h, zg_l, zg_h, zo_l, zo_h;
                unpack2(zi_l, zi_h, acc[0][b]);
                unpack2(zf_l, zf_h, acc[1][b]);
                unpack2(zg_l, zg_h, acc[2][b]);
                unpack2(zo_l, zo_h, acc[3][b]);
                float zi = zi_l + zi_h, zf = zf_l + zf_h;
                float zg = zg_l + zg_h, zo = zo_l + zo_h;
                float cv = sigm(zf) * cres[b] + sigm(zi) * lrelu(zg);
                cres[b] = cv;
                hB[b * H + j] = sigm(zo) * lrelu(cv);
            }
            __syncthreads();
        }
    }

    // ---- head at t=2 (buffers alias dead front-end smem) ----
    float *d1 = sm;        // 4*64 = 256
    float *d2 = sm + 256;  // 4*32
    float *d3 = sm + 384;  // 4*16
    float *d4 = sm + 448;  // 4*8
    float *d5 = sm + 480;  // 4*3

    for (int i = tid; i < TB * 64; i += NT) {
        int b = i >> 6, j = i & 63;
        float acc = P.b_p1[j];
        for (int k = 0; k < H; ++k) acc += hB[b * H + k] * P.w_p1[k * 64 + j];
        d1[i] = lrelu(acc);
    }
    __syncthreads();
    for (int i = tid; i < TB * 32; i += NT) {
        int b = i >> 5, j = i & 31;
        float acc = P.b_p2[j];
        #pragma unroll
        for (int k = 0; k < 64; ++k) acc += d1[b * 64 + k] * P.w_p2[k * 32 + j];
        d2[i] = lrelu(acc);
    }
    __syncthreads();
    for (int i = tid; i < TB * 16; i += NT) {
        int b = i >> 4, j = i & 15;
        float acc = P.b_p3[j];
        #pragma unroll
        for (int k = 0; k < 32; ++k) acc += d2[b * 32 + k] * P.w_p3[k * 16 + j];
        d3[i] = lrelu(acc);
    }
    __syncthreads();
    for (int i = tid; i < TB * 8; i += NT) {
        int b = i >> 3, j = i & 7;
        float acc = P.b_p4[j];
        #pragma unroll
        for (int k = 0; k < 16; ++k) acc += d3[b * 16 + k] * P.w_p4[k * 8 + j];
        d4[i] = lrelu(acc);
    }
    __syncthreads();
    for (int i = tid; i < TB * 3; i += NT) {
        int b = i / 3, j = i % 3;
        float acc = P.b_p5[j];
        #pragma unroll
        for (int k = 0; k < 8; ++k) acc += d4[b * 8 + k] * P.w_p5[k * 3 + j];
        d5[i] = lrelu(acc);
    }
    __syncthreads();

    // ---- softmax + write both outputs ----
    if (tid < TB) {
        int b = tid;
        float l0 = d5[b * 3 + 0], l1 = d5[b * 3 + 1], l2 = d5[b * 3 + 2];
        float m = fmaxf(l0, fmaxf(l1, l2));
        float e0 = __expf(l0 - m), e1 = __expf(l1 - m), e2 = __expf(l2 - m);
        float inv = 1.f / (e0 + e1 + e2);
        float o0 = e0 * inv, o1 = e1 * inv, o2 = e2 * inv;
        size_t gb = (size_t)(bg0 + b);
        float *outp = P.out + gb * 3;
        outp[0] = o0; outp[1] = o1; outp[2] = o2;
        float *xp = P.out + (size_t)Bsz * 3 + gb * 13;
        const float *fsrc = P.feature + gb * Tsz * Fsz + 2 * Fsz + 27;
        #pragma unroll
        for (int q = 0; q < 10; ++q) xp[q] = fsrc[q];
        xp[10] = o0; xp[11] = o1; xp[12] = o2;
    }
}

extern "C" void kernel_launch(void *const *d_in, const int *in_sizes, int n_in,
                              void *d_out, int out_size) {
    Params P;
    P.feature = (const float *)d_in[0];
    P.w_m1 = (const float *)d_in[1];  P.b_m1 = (const float *)d_in[2];
    P.w_m2 = (const float *)d_in[3];  P.b_m2 = (const float *)d_in[4];
    P.w_t1 = (const float *)d_in[5];  P.b_t1 = (const float *)d_in[6];
    P.w_t2 = (const float *)d_in[7];  P.b_t2 = (const float *)d_in[8];
    P.w_s1 = (const float *)d_in[9];  P.b_s1 = (const float *)d_in[10];
    P.w_s2 = (const float *)d_in[11]; P.b_s2 = (const float *)d_in[12];
    P.w_lk = (const float *)d_in[13];
    P.w_lr = (const float *)d_in[14];
    P.b_l  = (const float *)d_in[15];
    P.w_p1 = (const float *)d_in[16]; P.b_p1 = (const float *)d_in[17];
    P.w_p2 = (const float *)d_in[18]; P.b_p2 = (const float *)d_in[19];
    P.w_p3 = (const float *)d_in[20]; P.b_p3 = (const float *)d_in[21];
    P.w_p4 = (const float *)d_in[22]; P.b_p4 = (const float *)d_in[23];
    P.w_p5 = (const float *)d_in[24]; P.b_p5 = (const float *)d_in[25];
    P.out = (float *)d_out;

    repack_kernel<<<(4 * FP2 * H + 255) / 256, 256>>>(P.w_lk, P.w_lr);
    lstm_fused_kernel<<<Bsz / TB, NT>>>(P);
}

// round 8
// speedup vs baseline: 2.1658x; 1.1822x over previous
#include <cuda_runtime.h>
#include <math.h>

#define Bsz 4096
#define Tsz 64
#define Fsz 37
#define TB 8          // batch elements per CTA
#define NP 24         // TB * 3 timesteps
#define NT 128        // threads per CTA (one per hidden unit)
#define FDIM 150      // lin width
#define LINP 152      // padded lin stride (608B rows, 16B aligned)
#define FP4 38        // ceil(FDIM/4) quad-f groups (padded with zeros)
#define KP4 32        // H/4 quad-k groups
#define GATES 512
#define H 128

typedef unsigned long long ull;

// ---- global scratch: quad-f packed LSTM weights ----
// g_wk4[(c*FP4 + fq)*H + j] = (w[4fq],w[4fq+1] | w[4fq+2],w[4fq+3]) for gate c, unit j
__device__ ulonglong2 g_wk4[4 * FP4 * H];   // 311 KB
__device__ ulonglong2 g_wr4[4 * KP4 * H];   // 262 KB

// shared memory layout (floats)
#define OFF_FEAT 0        // 24*37 = 888 (aliased by head buffers later)
#define OFF_T1M1 888      // 24*16 = 384
#define OFF_S1   1272     // 24*32 = 768
#define OFF_LIN  2040     // 3*8*152 = 3648 (byte 8160, 16B aligned)
#define OFF_H    5688     // 8*128 = 1024   (byte 22752, 16B aligned)
#define SMEM_FLOATS 6712  // 26848 bytes

struct Params {
    const float *feature;
    const float *w_m1, *b_m1, *w_m2, *b_m2;
    const float *w_t1, *b_t1, *w_t2, *b_t2;
    const float *w_s1, *b_s1, *w_s2, *b_s2;
    const float *w_lk, *w_lr, *b_l;
    const float *w_p1, *b_p1, *w_p2, *b_p2, *w_p3, *b_p3, *w_p4, *b_p4, *w_p5, *b_p5;
    float *out;
};

__device__ __forceinline__ float lrelu(float x) { return x >= 0.f ? x : 0.2f * x; }
__device__ __forceinline__ float sigm(float x) { return 1.f / (1.f + __expf(-x)); }

__device__ __forceinline__ ull pack2(float lo, float hi) {
    ull v;
    asm("mov.b64 %0, {%1, %2};" : "=l"(v) : "f"(lo), "f"(hi));
    return v;
}
__device__ __forceinline__ void unpack2(float &lo, float &hi, ull v) {
    asm("mov.b64 {%0, %1}, %2;" : "=f"(lo), "=f"(hi) : "l"(v));
}
__device__ __forceinline__ void ffma2(ull &acc, ull a, ull b) {
    asm("fma.rn.f32x2 %0, %1, %2, %0;" : "+l"(acc) : "l"(a), "l"(b));
}

// ---- pre-kernel: repack w_lk/w_lr into quad-f streams ----
__global__ void repack_kernel(const float *__restrict__ wlk,
                              const float *__restrict__ wlr) {
    int i = blockIdx.x * 256 + threadIdx.x;
    if (i < 4 * FP4 * H) {
        int c = i / (FP4 * H), r = i % (FP4 * H);
        int fq = r / H, j = r % H;
        float w[4];
        #pragma unroll
        for (int q = 0; q < 4; ++q) {
            int f = 4 * fq + q;
            w[q] = (f < FDIM) ? wlk[f * GATES + c * H + j] : 0.f;
        }
        g_wk4[i] = make_ulonglong2(pack2(w[0], w[1]), pack2(w[2], w[3]));
    }
    if (i < 4 * KP4 * H) {
        int c = i / (KP4 * H), r = i % (KP4 * H);
        int kq = r / H, j = r % H;
        float w[4];
        #pragma unroll
        for (int q = 0; q < 4; ++q)
            w[q] = wlr[(4 * kq + q) * GATES + c * H + j];
        g_wr4[i] = make_ulonglong2(pack2(w[0], w[1]), pack2(w[2], w[3]));
    }
}

// lin batch-major: [t][b][f], f contiguous, stride LINP
#define LIDX(t, f, b) (((t) * TB + (b)) * LINP + (f))

__global__ void __launch_bounds__(NT, 4) lstm_fused_kernel(Params P) {
    __shared__ __align__(16) float sm[SMEM_FLOATS];
    const int tid = threadIdx.x;
    const int bg0 = blockIdx.x * TB;

    float *feat = sm + OFF_FEAT;
    float *t1m1 = sm + OFF_T1M1;
    float *S1   = sm + OFF_S1;
    float *linB = sm + OFF_LIN;
    float *hB   = sm + OFF_H;     // [b][k], rows 512B

    // ---- load feature rows t=0..2 for 8 batch elems; zero lin pad cols ----
    for (int i = tid; i < NP * Fsz; i += NT) {
        int p = i / Fsz, f = i % Fsz;
        int b = p / 3, t = p % 3;
        feat[p * Fsz + f] =
            P.feature[(size_t)(bg0 + b) * Tsz * Fsz + (size_t)t * Fsz + f];
    }
    if (tid < NP) {
        linB[tid * LINP + 150] = 0.f;
        linB[tid * LINP + 151] = 0.f;
    }
    __syncthreads();

    // ---- pass1: M1 (q<8) and T1 (q>=8), per (b,t) pair p ----
    for (int i = tid; i < NP * 16; i += NT) {
        int p = i >> 4, q = i & 15;
        const float *fr = feat + p * Fsz;
        float acc;
        if (q < 8) {
            acc = P.b_m1[q];
            #pragma unroll
            for (int f = 0; f < 3; ++f) acc += fr[33 + f] * P.w_m1[f * 8 + q];
            acc = lrelu(acc);
        } else {
            int j = q - 8;
            acc = P.b_t1[j];
            #pragma unroll
            for (int f = 0; f < Fsz; ++f) acc += fr[f] * P.w_t1[f * 8 + j];
            acc = lrelu(acc);
            acc = fabsf(acc);
        }
        t1m1[i] = acc;
    }
    __syncthreads();

    // ---- pass2: M -> lin[0:16], Tsk -> lin[16:32], Psk -> lin[32:48] ----
    for (int i = tid; i < NP * 32; i += NT) {
        int p = i >> 5, q = i & 31;
        int b = p / 3, t = p % 3;
        if (q < 16) {
            float acc = P.b_m2[q];
            #pragma unroll
            for (int k = 0; k < 8; ++k) acc += t1m1[p * 16 + k] * P.w_m2[k * 16 + q];
            linB[LIDX(t, q, b)] = lrelu(acc);
        } else {
            int j = q - 16;
            float acc = P.b_t2[j];
            #pragma unroll
            for (int k = 0; k < 8; ++k) acc += t1m1[p * 16 + 8 + k] * P.w_t2[k * 16 + j];
            float v = (acc >= 0.f) ? acc : -0.2f * acc;  // abs(lrelu)
            linB[LIDX(t, 16 + j, b)] = v;
            linB[LIDX(t, 32 + j, b)] = log1pf(v);
        }
    }
    // Pa -> lin[48], feature copy -> lin[113:150]
    for (int i = tid; i < NP * 38; i += NT) {
        int p = i / 38, q = i % 38;
        int b = p / 3, t = p % 3;
        if (q == 0) linB[LIDX(t, 48, b)] = log1pf(feat[p * Fsz + 31]);
        else        linB[LIDX(t, 113 + (q - 1), b)] = feat[p * Fsz + (q - 1)];
    }
    __syncthreads();

    // ---- pass3: S1 = lrelu(s_in @ w_s1 + b_s1) ----
    for (int i = tid; i < NP * 32; i += NT) {
        int p = i >> 5, j = i & 31;
        int b = p / 3, t = p % 3;
        float acc = P.b_s1[j];
        for (int f = 0; f < 49; ++f) acc += linB[LIDX(t, f, b)] * P.w_s1[f * 32 + j];
        const float *fr = feat + p * Fsz;
        #pragma unroll
        for (int e = 0; e < 6; ++e) acc += fr[27 + e] * P.w_s1[(49 + e) * 32 + j];
        #pragma unroll
        for (int e = 0; e < 3; ++e) acc += fr[33 + e] * P.w_s1[(55 + e) * 32 + j];
        S1[p * 32 + j] = lrelu(acc);
    }
    __syncthreads();

    // ---- pass4: S -> lin[49:113] ----
    for (int i = tid; i < NP * 64; i += NT) {
        int p = i >> 6, j = i & 63;
        int b = p / 3, t = p % 3;
        float acc = P.b_s2[j];
        #pragma unroll
        for (int k = 0; k < 32; ++k) acc += S1[p * 32 + k] * P.w_s2[k * 64 + j];
        linB[LIDX(t, 49 + j, b)] = lrelu(acc);
    }
    __syncthreads();

    // ---- LSTM: 3 timesteps. Thread tid owns hidden unit j for all 4 gates
    // and all 8 batches. f32x2 lanes hold (even-f, odd-f) partial sums;
    // quad-f packed weights (LDG.128), LDS.128 activations, c in registers.
    {
        const int j = tid;
        const ulonglong2 *wk0 = g_wk4 + 0 * FP4 * H + j;
        const ulonglong2 *wk1 = g_wk4 + 1 * FP4 * H + j;
        const ulonglong2 *wk2 = g_wk4 + 2 * FP4 * H + j;
        const ulonglong2 *wk3 = g_wk4 + 3 * FP4 * H + j;
        const ulonglong2 *wr0 = g_wr4 + 0 * KP4 * H + j;
        const ulonglong2 *wr1 = g_wr4 + 1 * KP4 * H + j;
        const ulonglong2 *wr2 = g_wr4 + 2 * KP4 * H + j;
        const ulonglong2 *wr3 = g_wr4 + 3 * KP4 * H + j;
        const float bi0 = P.b_l[j], bi1 = P.b_l[j + H];
        const float bi2 = P.b_l[j + 2 * H], bi3 = P.b_l[j + 3 * H];
        float cres[TB];
        #pragma unroll
        for (int b = 0; b < TB; ++b) cres[b] = 0.f;

        for (int t = 0; t < 3; ++t) {
            ull acc0[TB], acc1[TB], acc2[TB], acc3[TB];
            #pragma unroll
            for (int b = 0; b < TB; ++b) {
                acc0[b] = pack2(bi0, 0.f);
                acc1[b] = pack2(bi1, 0.f);
                acc2[b] = pack2(bi2, 0.f);
                acc3[b] = pack2(bi3, 0.f);
            }

            // input GEMM: z += lin_t @ w_lk   (38 quad-f groups)
            #pragma unroll 2
            for (int fq = 0; fq < FP4; ++fq) {
                ulonglong2 w0 = __ldg(wk0 + fq * H);
                ulonglong2 w1 = __ldg(wk1 + fq * H);
                ulonglong2 w2 = __ldg(wk2 + fq * H);
                ulonglong2 w3 = __ldg(wk3 + fq * H);
                ulonglong2 a[TB];
                #pragma unroll
                for (int b = 0; b < TB; ++b)
                    a[b] = *(const ulonglong2 *)(linB + LIDX(t, 4 * fq, b));
                #pragma unroll
                for (int b = 0; b < TB; ++b) {
                    ffma2(acc0[b], a[b].x, w0.x);
                    ffma2(acc1[b], a[b].x, w1.x);
                    ffma2(acc2[b], a[b].x, w2.x);
                    ffma2(acc3[b], a[b].x, w3.x);
                }
                #pragma unroll
                for (int b = 0; b < TB; ++b) {
                    ffma2(acc0[b], a[b].y, w0.y);
                    ffma2(acc1[b], a[b].y, w1.y);
                    ffma2(acc2[b], a[b].y, w2.y);
                    ffma2(acc3[b], a[b].y, w3.y);
                }
            }
            // recurrent GEMM: z += h @ w_lr   (32 quad-k groups; h==0 at t=0)
            if (t > 0) {
                #pragma unroll 2
                for (int kq = 0; kq < KP4; ++kq) {
                    ulonglong2 w0 = __ldg(wr0 + kq * H);
                    ulonglong2 w1 = __ldg(wr1 + kq * H);
                    ulonglong2 w2 = __ldg(wr2 + kq * H);
                    ulonglong2 w3 = __ldg(wr3 + kq * H);
                    ulonglong2 a[TB];
                    #pragma unroll
                    for (int b = 0; b < TB; ++b)
                        a[b] = *(const ulonglong2 *)(hB + b * H + 4 * kq);
                    #pragma unroll
                    for (int b = 0; b < TB; ++b) {
                        ffma2(acc0[b], a[b].x, w0.x);
                        ffma2(acc1[b], a[b].x, w1.x);
                        ffma2(acc2[b], a[b].x, w2.x);
                        ffma2(acc3[b], a[b].x, w3.x);
                    }
                    #pragma unroll
                    for (int b = 0; b < TB; ++b) {
                        ffma2(acc0[b], a[b].y, w0.y);
                        ffma2(acc1[b], a[b].y, w1.y);
                        ffma2(acc2[b], a[b].y, w2.y);
                        ffma2(acc3[b], a[b].y, w3.y);
                    }
                }
            }

            // all reads of hB (this t) must finish before overwrite
            __syncthreads();

            // lane-add + gates + state update, fully in registers
            #pragma unroll
            for (int b = 0; b < TB; ++b) {
                float zi_l, zi_h, zf_l, zf_h, zg_l, zg_h, zo_l, zo_h;
                unpack2(zi_l, zi_h, acc0[b]);
                unpack2(zf_l, zf_h, acc1[b]);
                unpack2(zg_l, zg_h, acc2[b]);
                unpack2(zo_l, zo_h, acc3[b]);
                float zi = zi_l + zi_h, zf = zf_l + zf_h;
                float zg = zg_l + zg_h, zo = zo_l + zo_h;
                float cv = sigm(zf) * cres[b] + sigm(zi) * lrelu(zg);
                cres[b] = cv;
                hB[b * H + j] = sigm(zo) * lrelu(cv);
            }
            __syncthreads();
        }
    }

    // ---- head at t=2 (buffers alias dead front-end smem) ----
    float *d1 = sm;        // 8*64 = 512
    float *d2 = sm + 512;  // 8*32
    float *d3 = sm + 768;  // 8*16
    float *d4 = sm + 896;  // 8*8
    float *d5 = sm + 960;  // 8*3

    for (int i = tid; i < TB * 64; i += NT) {
        int b = i >> 6, j = i & 63;
        float acc = P.b_p1[j];
        for (int k = 0; k < H; ++k) acc += hB[b * H + k] * P.w_p1[k * 64 + j];
        d1[i] = lrelu(acc);
    }
    __syncthreads();
    for (int i = tid; i < TB * 32; i += NT) {
        int b = i >> 5, j = i & 31;
        float acc = P.b_p2[j];
        #pragma unroll
        for (int k = 0; k < 64; ++k) acc += d1[b * 64 + k] * P.w_p2[k * 32 + j];
        d2[i] = lrelu(acc);
    }
    __syncthreads();
    for (int i = tid; i < TB * 16; i += NT) {
        int b = i >> 4, j = i & 15;
        float acc = P.b_p3[j];
        #pragma unroll
        for (int k = 0; k < 32; ++k) acc += d2[b * 32 + k] * P.w_p3[k * 16 + j];
        d3[i] = lrelu(acc);
    }
    __syncthreads();
    for (int i = tid; i < TB * 8; i += NT) {
        int b = i >> 3, j = i & 7;
        float acc = P.b_p4[j];
        #pragma unroll
        for (int k = 0; k < 16; ++k) acc += d3[b * 16 + k] * P.w_p4[k * 8 + j];
        d4[i] = lrelu(acc);
    }
    __syncthreads();
    for (int i = tid; i < TB * 3; i += NT) {
        int b = i / 3, j = i % 3;
        float acc = P.b_p5[j];
        #pragma unroll
        for (int k = 0; k < 8; ++k) acc += d4[b * 8 + k] * P.w_p5[k * 3 + j];
        d5[i] = lrelu(acc);
    }
    __syncthreads();

    // ---- softmax + write both outputs ----
    if (tid < TB) {
        int b = tid;
        float l0 = d5[b * 3 + 0], l1 = d5[b * 3 + 1], l2 = d5[b * 3 + 2];
        float m = fmaxf(l0, fmaxf(l1, l2));
        float e0 = __expf(l0 - m), e1 = __expf(l1 - m), e2 = __expf(l2 - m);
        float inv = 1.f / (e0 + e1 + e2);
        float o0 = e0 * inv, o1 = e1 * inv, o2 = e2 * inv;
        size_t gb = (size_t)(bg0 + b);
        float *outp = P.out + gb * 3;
        outp[0] = o0; outp[1] = o1; outp[2] = o2;
        float *xp = P.out + (size_t)Bsz * 3 + gb * 13;
        const float *fsrc = P.feature + gb * Tsz * Fsz + 2 * Fsz + 27;
        #pragma unroll
        for (int q = 0; q < 10; ++q) xp[q] = fsrc[q];
        xp[10] = o0; xp[11] = o1; xp[12] = o2;
    }
}

extern "C" void kernel_launch(void *const *d_in, const int *in_sizes, int n_in,
                              void *d_out, int out_size) {
    Params P;
    P.feature = (const float *)d_in[0];
    P.w_m1 = (const float *)d_in[1];  P.b_m1 = (const float *)d_in[2];
    P.w_m2 = (const float *)d_in[3];  P.b_m2 = (const float *)d_in[4];
    P.w_t1 = (const float *)d_in[5];  P.b_t1 = (const float *)d_in[6];
    P.w_t2 = (const float *)d_in[7];  P.b_t2 = (const float *)d_in[8];
    P.w_s1 = (const float *)d_in[9];  P.b_s1 = (const float *)d_in[10];
    P.w_s2 = (const float *)d_in[11]; P.b_s2 = (const float *)d_in[12];
    P.w_lk = (const float *)d_in[13];
    P.w_lr = (const float *)d_in[14];
    P.b_l  = (const float *)d_in[15];
    P.w_p1 = (const float *)d_in[16]; P.b_p1 = (const float *)d_in[17];
    P.w_p2 = (const float *)d_in[18]; P.b_p2 = (const float *)d_in[19];
    P.w_p3 = (const float *)d_in[20]; P.b_p3 = (const float *)d_in[21];
    P.w_p4 = (const float *)d_in[22]; P.b_p4 = (const float *)d_in[23];
    P.w_p5 = (const float *)d_in[24]; P.b_p5 = (const float *)d_in[25];
    P.out = (float *)d_out;

    repack_kernel<<<(4 * FP4 * H + 255) / 256, 256>>>(P.w_lk, P.w_lr);
    lstm_fused_kernel<<<Bsz / TB, NT>>>(P);
}